// round 14
// baseline (speedup 1.0000x reference)
#include <cuda_runtime.h>
#include <cuda_fp16.h>
#include <mma.h>
#include <math.h>
#include <stdint.h>
#include <string.h>

using namespace nvcuda;

#define B_    2
#define T_    1024
#define C_    1024
#define H_    16
#define D_    64
#define RM_   32
#define FBM_  32
#define BT_   (B_*T_)       // 2048
#define C3_   (3*C_)        // 3072
#define NBIAS_ (2*T_-1)     // 2047

// ---------------- scratch (static device globals; no allocation) ------------
__device__ __half g_xh [BT_*C_];             // x in fp16 (gemm1 A)
__device__ __half g_wah[C3_*C_];             // W_attn fp16
__device__ __half g_wph[C_*C_];              // W_proj fp16
__device__ __half g_yh [BT_*C_];             // attention output fp16 (gemm2 A)
__device__ __half g_qf[BT_*C_];              // [B,H,T,D] fp16 (rope applied)
__device__ __half g_kf[BT_*C_];
__device__ __half g_vf[BT_*C_];
__device__ float g_cost[BT_*RM_];
__device__ float g_sint[BT_*RM_];
__device__ float g_bias[B_*NBIAS_];          // bias lookup by (q-k)+T-1

// ---------------- helpers ----------------------------------------------------
__device__ __forceinline__ uint32_t smem_u32(const void* p) {
    uint32_t a;
    asm("{ .reg .u64 t; cvta.to.shared.u64 t, %1; cvt.u32.u64 %0, t; }"
        : "=r"(a) : "l"(p));
    return a;
}

__device__ __forceinline__ uint32_t packh2(float p0, float p1) {
    __half2 h = __floats2half2_rn(p0, p1);   // .x = p0 (low half)
    uint32_t u; memcpy(&u, &h, 4);
    return u;
}

__device__ __forceinline__ void ldsm4(uint32_t* r, uint32_t addr) {
    asm volatile("ldmatrix.sync.aligned.m8n8.x4.shared.b16 {%0,%1,%2,%3}, [%4];"
        : "=r"(r[0]),"=r"(r[1]),"=r"(r[2]),"=r"(r[3]) : "r"(addr));
}
__device__ __forceinline__ void ldsm4t(uint32_t* r, uint32_t addr) {
    asm volatile("ldmatrix.sync.aligned.m8n8.x4.trans.shared.b16 {%0,%1,%2,%3}, [%4];"
        : "=r"(r[0]),"=r"(r[1]),"=r"(r[2]),"=r"(r[3]) : "r"(addr));
}
__device__ __forceinline__ void mma16816(float* d, const uint32_t* a,
                                         uint32_t b0, uint32_t b1) {
    asm volatile("mma.sync.aligned.m16n8k16.row.col.f32.f16.f16.f32 "
        "{%0,%1,%2,%3}, {%4,%5,%6,%7}, {%8,%9}, {%0,%1,%2,%3};"
        : "+f"(d[0]),"+f"(d[1]),"+f"(d[2]),"+f"(d[3])
        : "r"(a[0]),"r"(a[1]),"r"(a[2]),"r"(a[3]),"r"(b0),"r"(b1));
}

// ---------------- fp32 -> fp16 bulk convert ----------------------------------
__global__ void cvt_h_kernel(const float* __restrict__ s, __half* __restrict__ d,
                             int n8) {
    int i = blockIdx.x * blockDim.x + threadIdx.x;
    if (i >= n8) return;
    float4 a = *(const float4*)(s + (size_t)i*8);
    float4 b = *(const float4*)(s + (size_t)i*8 + 4);
    uint4 p;
    p.x = packh2(a.x, a.y); p.y = packh2(a.z, a.w);
    p.z = packh2(b.x, b.y); p.w = packh2(b.z, b.w);
    *(uint4*)(d + (size_t)i*8) = p;
}

// =============================================================================
// WMMA fp16 GEMM (fp16 inputs):  C[M,N] = A[M,K] * B[N,K]^T + bias (+ Res)
// 128x128 tile, 8 warps of 32x64, K chunked by 32, double-buffered smem,
// LDG(next) issued before MMA(cur). FUSE: RoPE + fp16 head-split epilogue.
// =============================================================================
#define GST 40

template<bool FUSE>
__global__ __launch_bounds__(256, 2)
void gemm_wmma_kernel(const __half* __restrict__ A, const __half* __restrict__ Bm,
                      const float* __restrict__ bias, const float* __restrict__ Res,
                      float* __restrict__ Cout, int M, int N, int K) {
    extern __shared__ __align__(16) char smraw[];
    __half* Ah = (__half*)smraw;                 // [2][128*GST]
    __half* Bh = Ah + 2*128*GST;                 // [2][128*GST]
    float* stage = (float*)(Bh + 2*128*GST);     // 8 warps * 16*20 fp32

    const int tid  = threadIdx.x;
    const int w    = tid >> 5;
    const int lane = tid & 31;
    const int wm   = (w & 3) * 32;
    const int wn   = (w >> 2) * 64;
    const int m0 = blockIdx.y * 128, n0 = blockIdx.x * 128;

    wmma::fragment<wmma::accumulator, 16, 16, 16, float> acc[2][4];
    #pragma unroll
    for (int i = 0; i < 2; i++)
        #pragma unroll
        for (int j = 0; j < 4; j++) wmma::fill_fragment(acc[i][j], 0.0f);

    const int r_ld  = tid >> 2;          // row 0..63 (+64 for q=1)
    const int cg_ld = tid & 3;           // uint4 col group

    uint4 av[2], bv[2];
    // ---- prologue: LDG chunk 0 ----
    #pragma unroll
    for (int q = 0; q < 2; q++) {
        int r = r_ld + q*64;
        av[q] = *(const uint4*)(A  + (size_t)(m0 + r) * K + cg_ld*8);
        bv[q] = *(const uint4*)(Bm + (size_t)(n0 + r) * K + cg_ld*8);
    }

    const int nch = K >> 5;
    for (int c = 0; c < nch; c++) {
        const int bs = c & 1;
        __half* Asm = Ah + bs * 128*GST;
        __half* Bsm = Bh + bs * 128*GST;
        // ---- STS (raw fp16, no cvt) ----
        #pragma unroll
        for (int q = 0; q < 2; q++) {
            int r = r_ld + q*64;
            *(uint4*)&Asm[r*GST + cg_ld*8] = av[q];
            *(uint4*)&Bsm[r*GST + cg_ld*8] = bv[q];
        }
        __syncthreads();
        // ---- LDG chunk c+1 (overlaps MMA below) ----
        if (c + 1 < nch) {
            const int k0 = (c + 1) * 32;
            #pragma unroll
            for (int q = 0; q < 2; q++) {
                int r = r_ld + q*64;
                av[q] = *(const uint4*)(A  + (size_t)(m0 + r) * K + k0 + cg_ld*8);
                bv[q] = *(const uint4*)(Bm + (size_t)(n0 + r) * K + k0 + cg_ld*8);
            }
        }
        // ---- MMA chunk c ----
        #pragma unroll
        for (int kk = 0; kk < 2; kk++) {
            wmma::fragment<wmma::matrix_a, 16,16,16, __half, wmma::row_major> ah[2];
            #pragma unroll
            for (int i = 0; i < 2; i++)
                wmma::load_matrix_sync(ah[i], &Asm[(wm + i*16)*GST + kk*16], GST);
            #pragma unroll
            for (int j = 0; j < 4; j++) {
                wmma::fragment<wmma::matrix_b, 16,16,16, __half, wmma::col_major> bf;
                wmma::load_matrix_sync(bf, &Bsm[(wn + j*16)*GST + kk*16], GST);
                #pragma unroll
                for (int i = 0; i < 2; i++)
                    wmma::mma_sync(acc[i][j], ah[i], bf, acc[i][j]);
            }
        }
    }

    // ---- epilogue ----
    float* st = stage + w * 16 * 20;
    #pragma unroll
    for (int i = 0; i < 2; i++) {
        #pragma unroll
        for (int j = 0; j < 4; j++) {
            wmma::store_matrix_sync(st, acc[i][j], 20, wmma::mem_row_major);
            __syncwarp();
            int row = lane >> 1, ch = (lane & 1) * 8;
            int gm = m0 + wm + i*16 + row;
            int gn = n0 + wn + j*16 + ch;
            float4 o1 = *(float4*)&st[row*20 + ch];
            float4 o2 = *(float4*)&st[row*20 + ch + 4];
            float4 b1 = *(const float4*)(bias + gn);
            float4 b2 = *(const float4*)(bias + gn + 4);
            o1.x += b1.x; o1.y += b1.y; o1.z += b1.z; o1.w += b1.w;
            o2.x += b2.x; o2.y += b2.y; o2.z += b2.z; o2.w += b2.w;
            if (FUSE) {
                // RoPE + fp16 pack + [B,H,T,D] scatter
                int part = gn >> 10, hd = gn & 1023;
                int hh = hd >> 6, d = hd & 63;
                size_t dst = (((size_t)(gm >> 10) * H_ + hh) * T_ + (gm & 1023)) * D_ + d;
                uint4 pk;
                if (part < 2) {
                    float4 cs = *(const float4*)&g_cost[gm*RM_ + (d >> 1)];
                    float4 sn = *(const float4*)&g_sint[gm*RM_ + (d >> 1)];
                    pk.x = packh2(o1.x*cs.x - o1.y*sn.x, o1.x*sn.x + o1.y*cs.x);
                    pk.y = packh2(o1.z*cs.y - o1.w*sn.y, o1.z*sn.y + o1.w*cs.y);
                    pk.z = packh2(o2.x*cs.z - o2.y*sn.z, o2.x*sn.z + o2.y*cs.z);
                    pk.w = packh2(o2.z*cs.w - o2.w*sn.w, o2.z*sn.w + o2.w*cs.w);
                    *(uint4*)((part == 0 ? g_qf : g_kf) + dst) = pk;
                } else {
                    pk.x = packh2(o1.x, o1.y); pk.y = packh2(o1.z, o1.w);
                    pk.z = packh2(o2.x, o2.y); pk.w = packh2(o2.z, o2.w);
                    *(uint4*)(g_vf + dst) = pk;
                }
            } else {
                float4 r1 = *(const float4*)(Res + (size_t)gm * N + gn);
                float4 r2 = *(const float4*)(Res + (size_t)gm * N + gn + 4);
                o1.x += r1.x; o1.y += r1.y; o1.z += r1.z; o1.w += r1.w;
                o2.x += r2.x; o2.y += r2.y; o2.z += r2.z; o2.w += r2.w;
                *(float4*)(Cout + (size_t)gm * N + gn)     = o1;
                *(float4*)(Cout + (size_t)gm * N + gn + 4) = o2;
            }
            __syncwarp();
        }
    }
}

// ---------------- tiny table kernels ----------------------------------------
__global__ void rope_table_kernel(const float* __restrict__ coords,
                                  const float* __restrict__ W_rope) {
    int idx = blockIdx.x * blockDim.x + threadIdx.x;   // < BT_*RM_
    int bt = idx >> 5, m = idx & 31;
    float th = coords[bt] * W_rope[m];
    g_cost[idx] = cosf(th);
    g_sint[idx] = sinf(th);
}

__global__ void bias_table_kernel(const float* __restrict__ coords,
                                  const float* __restrict__ W_fb,
                                  const float* __restrict__ bc,
                                  const float* __restrict__ bs) {
    int idx = blockIdx.x * blockDim.x + threadIdx.x;
    int b   = blockIdx.y;
    if (idx >= NBIAS_) return;
    int dd = idx - (T_ - 1);
    const float* cb = coords + b * T_;
    float delta = (dd >= 0) ? (cb[dd] - cb[0]) : (cb[0] - cb[-dd]);
    float acc = 0.f;
    #pragma unroll
    for (int m = 0; m < FBM_; m++) {
        float S = delta * W_fb[m];
        acc += cosf(S) * bc[m] + sinf(S) * bs[m];
    }
    g_bias[b*NBIAS_ + idx] = acc * 0.17677669529663687f;   // 1/sqrt(FB_M)
}

// =============================================================================
// Raw-PTX flash attention, fp16, q-tile 128 (8 warps x 16 rows), k-chunks 64,
// double-buffered K/V smem, LDG(next) before compute(cur), one sync per chunk.
// 2 CTAs/SM enforced (regs <= 128). Output y stored fp16.
// =============================================================================
#define AKST 72   // smem row stride in fp16 elements

__global__ __launch_bounds__(256, 2)
void attn_mma_kernel() {
    __shared__ __align__(16) __half Kh[2][64*AKST];
    __shared__ __align__(16) __half Vh[2][64*AKST];
    __shared__ float bias_sm[1152];

    const int bh = blockIdx.y;
    const int b  = bh >> 4;
    const int h  = bh & 15;
    const int q0 = blockIdx.x * 128;
    const int tid  = threadIdx.x;
    const int w    = tid >> 5;
    const int lane = tid & 31;
    const int wq   = w * 16;

    // bias slice: idx for (local row rr, global col k) = 1023 + rr - k
    for (int i = tid; i < 1151; i += 256)
        bias_sm[i] = g_bias[b*NBIAS_ + q0 + i];

    // ---- stage Q (128x64 fp16) into Kh[0] (rows 0-63) + Vh[0] (rows 64-127) ----
    const uint4* qg = (const uint4*)(g_qf + ((size_t)bh * T_ + q0) * D_);
    #pragma unroll
    for (int qq = 0; qq < 4; qq++) {
        int id = qq * 256 + tid;
        int r = id >> 3, c = id & 7;
        __half* dst = (r < 64) ? &Kh[0][r*AKST + c*8] : &Vh[0][(r-64)*AKST + c*8];
        *(uint4*)dst = qg[r*8 + c];
    }
    __syncthreads();

    const uint32_t kb0 = smem_u32(Kh[0]), kb1 = smem_u32(Kh[1]);
    const uint32_t vb0 = smem_u32(Vh[0]), vb1 = smem_u32(Vh[1]);

    uint32_t qf[4][4];
    {
        const uint32_t qbase = (w < 4) ? kb0 : vb0;
        const int rbuf = (wq & 63) + (lane & 15);
        #pragma unroll
        for (int kk = 0; kk < 4; kk++) {
            uint32_t off = (uint32_t)((rbuf*AKST + kk*16 + (lane >> 4)*8) * 2);
            ldsm4(qf[kk], qbase + off);
        }
    }
    __syncthreads();   // Q frags read before chunk0 STS overwrites

    float oacc[8][4];
    #pragma unroll
    for (int j = 0; j < 8; j++)
        #pragma unroll
        for (int i = 0; i < 4; i++) oacc[j][i] = 0.f;
    float dsum0 = 0.f, dsum1 = 0.f;

    const __half* khg = g_kf + (size_t)bh * T_ * D_;
    const __half* vhg = g_vf + (size_t)bh * T_ * D_;
    const int i0base0 = 1023 + wq + (lane >> 2) - (lane & 3) * 2;

    // ---- prologue: LDG chunk 0 ----
    uint4 tK[2], tV[2];
    #pragma unroll
    for (int qq = 0; qq < 2; qq++) {
        int id = qq * 256 + tid;
        int r = id >> 3, c = id & 7;
        size_t g = (size_t)r * D_ + c * 8;
        tK[qq] = *(const uint4*)(khg + g);
        tV[qq] = *(const uint4*)(vhg + g);
    }

    for (int kc = 0; kc < 16; kc++) {
        const int k0 = kc * 64;
        const int bs = kc & 1;
        // ---- STS chunk kc ----
        #pragma unroll
        for (int qq = 0; qq < 2; qq++) {
            int id = qq * 256 + tid;
            int r = id >> 3, c = id & 7;
            *(uint4*)&Kh[bs][r*AKST + c*8] = tK[qq];
            *(uint4*)&Vh[bs][r*AKST + c*8] = tV[qq];
        }
        __syncthreads();
        // ---- LDG chunk kc+1 (overlaps compute below) ----
        if (kc < 15) {
            const int kn = (kc + 1) * 64;
            #pragma unroll
            for (int qq = 0; qq < 2; qq++) {
                int id = qq * 256 + tid;
                int r = id >> 3, c = id & 7;
                size_t g = (size_t)(kn + r) * D_ + c * 8;
                tK[qq] = *(const uint4*)(khg + g);
                tV[qq] = *(const uint4*)(vhg + g);
            }
        }
        const uint32_t kbh = bs ? kb1 : kb0;
        const uint32_t vbh = bs ? vb1 : vb0;

        // ---- S = Q K^T, accum in registers ----
        float sacc[8][4];
        #pragma unroll
        for (int j = 0; j < 8; j++)
            #pragma unroll
            for (int i = 0; i < 4; i++) sacc[j][i] = 0.f;

        #pragma unroll
        for (int kk = 0; kk < 4; kk++) {
            #pragma unroll
            for (int jp = 0; jp < 4; jp++) {
                uint32_t off = (uint32_t)(((jp*16 + ((lane>>4)<<3) + (lane&7)) * AKST
                               + kk*16 + ((lane>>3)&1)*8) * 2);
                uint32_t bhf[4];
                ldsm4(bhf, kbh + off);
                mma16816(sacc[jp*2],   qf[kk], bhf[0], bhf[1]);
                mma16816(sacc[jp*2+1], qf[kk], bhf[2], bhf[3]);
            }
        }

        // ---- softmax numerators in registers ----
        const int i0b = i0base0 - k0;
        #pragma unroll
        for (int j = 0; j < 8; j++) {
            int i0 = i0b - j*8;
            float p0 = __expf(sacc[j][0] * 0.125f + bias_sm[i0]);
            float p1 = __expf(sacc[j][1] * 0.125f + bias_sm[i0 - 1]);
            float p2 = __expf(sacc[j][2] * 0.125f + bias_sm[i0 + 8]);
            float p3 = __expf(sacc[j][3] * 0.125f + bias_sm[i0 + 7]);
            dsum0 += p0 + p1;
            dsum1 += p2 + p3;
            sacc[j][0] = p0; sacc[j][1] = p1; sacc[j][2] = p2; sacc[j][3] = p3;
        }

        // ---- O += P V (P from registers, V via ldmatrix.trans) ----
        #pragma unroll
        for (int kk = 0; kk < 4; kk++) {
            uint32_t pa[4];
            pa[0] = packh2(sacc[2*kk][0],   sacc[2*kk][1]);
            pa[1] = packh2(sacc[2*kk][2],   sacc[2*kk][3]);
            pa[2] = packh2(sacc[2*kk+1][0], sacc[2*kk+1][1]);
            pa[3] = packh2(sacc[2*kk+1][2], sacc[2*kk+1][3]);
            #pragma unroll
            for (int dp = 0; dp < 4; dp++) {
                uint32_t off = (uint32_t)(((kk*16 + ((lane>>3)&1)*8 + (lane&7)) * AKST
                               + dp*16 + (lane>>4)*8) * 2);
                uint32_t bvf[4];
                ldsm4t(bvf, vbh + off);
                mma16816(oacc[dp*2],   pa, bvf[0], bvf[1]);
                mma16816(oacc[dp*2+1], pa, bvf[2], bvf[3]);
            }
        }
    }

    // ---- normalize + store fp16 ----
    dsum0 += __shfl_xor_sync(0xffffffffu, dsum0, 1);
    dsum0 += __shfl_xor_sync(0xffffffffu, dsum0, 2);
    dsum1 += __shfl_xor_sync(0xffffffffu, dsum1, 1);
    dsum1 += __shfl_xor_sync(0xffffffffu, dsum1, 2);
    float inv0 = 1.0f / dsum0, inv1 = 1.0f / dsum1;

    int r0g = q0 + wq + (lane >> 2);
    __half* y0 = g_yh + (size_t)(b*T_ + r0g) * C_ + h*D_ + (lane & 3)*2;
    __half* y1 = y0 + (size_t)8 * C_;
    #pragma unroll
    for (int j = 0; j < 8; j++) {
        *(uint32_t*)(y0 + j*8) = packh2(oacc[j][0] * inv0, oacc[j][1] * inv0);
        *(uint32_t*)(y1 + j*8) = packh2(oacc[j][2] * inv1, oacc[j][3] * inv1);
    }
}

// ---------------- launcher ----------------------------------------------------
#define GEMM_SMEM (2*2*128*GST*2 + 8*16*20*4)               // 51200

extern "C" void kernel_launch(void* const* d_in, const int* in_sizes, int n_in,
                              void* d_out, int out_size) {
    (void)in_sizes; (void)n_in; (void)out_size;
    const float* x      = (const float*)d_in[0];
    const float* coords = (const float*)d_in[1];
    const float* W_attn = (const float*)d_in[2];
    const float* b_attn = (const float*)d_in[3];
    const float* W_proj = (const float*)d_in[4];
    const float* b_proj = (const float*)d_in[5];
    const float* W_rope = (const float*)d_in[6];
    const float* W_fb   = (const float*)d_in[7];
    const float* bcos   = (const float*)d_in[8];
    const float* bsin   = (const float*)d_in[9];
    float* out = (float*)d_out;

    void *p_xh = nullptr, *p_wah = nullptr, *p_wph = nullptr, *p_yh = nullptr;
    cudaGetSymbolAddress(&p_xh,  g_xh);
    cudaGetSymbolAddress(&p_wah, g_wah);
    cudaGetSymbolAddress(&p_wph, g_wph);
    cudaGetSymbolAddress(&p_yh,  g_yh);

    static bool attr_set = false;
    if (!attr_set) {
        cudaFuncSetAttribute(gemm_wmma_kernel<true>,
                             cudaFuncAttributeMaxDynamicSharedMemorySize, GEMM_SMEM);
        cudaFuncSetAttribute(gemm_wmma_kernel<false>,
                             cudaFuncAttributeMaxDynamicSharedMemorySize, GEMM_SMEM);
        attr_set = true;
    }

    // one-time fp32 -> fp16 converts (x, W_attn, W_proj)
    cvt_h_kernel<<<(BT_*C_/8 + 255)/256, 256>>>(x, (__half*)p_xh, BT_*C_/8);
    cvt_h_kernel<<<(C3_*C_/8 + 255)/256, 256>>>(W_attn, (__half*)p_wah, C3_*C_/8);
    cvt_h_kernel<<<(C_*C_/8 + 255)/256, 256>>>(W_proj, (__half*)p_wph, C_*C_/8);

    rope_table_kernel<<<(BT_*RM_)/256, 256>>>(coords, W_rope);
    bias_table_kernel<<<dim3((NBIAS_ + 255)/256, B_), 256>>>(coords, W_fb, bcos, bsin);

    // qkv GEMM with fused RoPE + fp16 head-split epilogue
    gemm_wmma_kernel<true><<<dim3(C3_/128, BT_/128), 256, GEMM_SMEM>>>(
        (const __half*)p_xh, (const __half*)p_wah, b_attn, nullptr, nullptr,
        BT_, C3_, C_);

    attn_mma_kernel<<<dim3(T_/128, B_*H_), 256>>>();

    gemm_wmma_kernel<false><<<dim3(C_/128, BT_/128), 256, GEMM_SMEM>>>(
        (const __half*)p_yh, (const __half*)p_wph, b_proj, x, out, BT_, C_, C_);
}

// round 16
// speedup vs baseline: 1.0464x; 1.0464x over previous
#include <cuda_runtime.h>
#include <cuda_fp16.h>
#include <mma.h>
#include <math.h>
#include <stdint.h>
#include <string.h>

using namespace nvcuda;

#define B_    2
#define T_    1024
#define C_    1024
#define H_    16
#define D_    64
#define RM_   32
#define FBM_  32
#define BT_   (B_*T_)       // 2048
#define C3_   (3*C_)        // 3072
#define NBIAS_ (2*T_-1)     // 2047

// ---------------- scratch (static device globals; no allocation) ------------
__device__ __half g_xh [BT_*C_];             // x in fp16 (gemm1 A)
__device__ __half g_wah[C3_*C_];             // W_attn fp16
__device__ __half g_wph[C_*C_];              // W_proj fp16
__device__ __half g_yh [BT_*C_];             // attention output fp16 (gemm2 A)
__device__ __half g_qf[BT_*C_];              // [B,H,T,D] fp16 (rope applied)
__device__ __half g_kf[BT_*C_];
__device__ __half g_vf[BT_*C_];
__device__ float g_cost[BT_*RM_];
__device__ float g_sint[BT_*RM_];
__device__ float g_bias[B_*NBIAS_];          // bias lookup by (q-k)+T-1

// ---------------- helpers ----------------------------------------------------
__device__ __forceinline__ uint32_t smem_u32(const void* p) {
    uint32_t a;
    asm("{ .reg .u64 t; cvta.to.shared.u64 t, %1; cvt.u32.u64 %0, t; }"
        : "=r"(a) : "l"(p));
    return a;
}

__device__ __forceinline__ uint32_t packh2(float p0, float p1) {
    __half2 h = __floats2half2_rn(p0, p1);   // .x = p0 (low half)
    uint32_t u; memcpy(&u, &h, 4);
    return u;
}

__device__ __forceinline__ void ldsm4(uint32_t* r, uint32_t addr) {
    asm volatile("ldmatrix.sync.aligned.m8n8.x4.shared.b16 {%0,%1,%2,%3}, [%4];"
        : "=r"(r[0]),"=r"(r[1]),"=r"(r[2]),"=r"(r[3]) : "r"(addr));
}
__device__ __forceinline__ void ldsm4t(uint32_t* r, uint32_t addr) {
    asm volatile("ldmatrix.sync.aligned.m8n8.x4.trans.shared.b16 {%0,%1,%2,%3}, [%4];"
        : "=r"(r[0]),"=r"(r[1]),"=r"(r[2]),"=r"(r[3]) : "r"(addr));
}
__device__ __forceinline__ void mma16816(float* d, const uint32_t* a,
                                         uint32_t b0, uint32_t b1) {
    asm volatile("mma.sync.aligned.m16n8k16.row.col.f32.f16.f16.f32 "
        "{%0,%1,%2,%3}, {%4,%5,%6,%7}, {%8,%9}, {%0,%1,%2,%3};"
        : "+f"(d[0]),"+f"(d[1]),"+f"(d[2]),"+f"(d[3])
        : "r"(a[0]),"r"(a[1]),"r"(a[2]),"r"(a[3]),"r"(b0),"r"(b1));
}

// =============================================================================
// Fused prologue (ONE launch, blockIdx-partitioned):
//   [0,1024)    cvt x        -> g_xh    (2048*1024 elems, 8/thread)
//   [1024,2560) cvt W_attn   -> g_wah   (3072*1024)
//   [2560,3072) cvt W_proj   -> g_wph   (1024*1024)
//   [3072,3328) rope tables  -> g_cost/g_sint
//   [3328,3344) bias table   -> g_bias
// =============================================================================
#define PRO_BLOCKS 3344

__global__ __launch_bounds__(256)
void prologue_kernel(const float* __restrict__ x,
                     const float* __restrict__ W_attn,
                     const float* __restrict__ W_proj,
                     const float* __restrict__ coords,
                     const float* __restrict__ W_rope,
                     const float* __restrict__ W_fb,
                     const float* __restrict__ bc,
                     const float* __restrict__ bs) {
    const int blk = blockIdx.x;
    const int tid = threadIdx.x;
    if (blk < 3072) {
        // bulk fp32 -> fp16 convert, 8 elems/thread
        const float* s;
        __half* d;
        int lb;
        if (blk < 1024)      { s = x;      d = g_xh;  lb = blk; }
        else if (blk < 2560) { s = W_attn; d = g_wah; lb = blk - 1024; }
        else                 { s = W_proj; d = g_wph; lb = blk - 2560; }
        size_t i = ((size_t)lb * 256 + tid) * 8;
        float4 a = *(const float4*)(s + i);
        float4 b = *(const float4*)(s + i + 4);
        uint4 p;
        p.x = packh2(a.x, a.y); p.y = packh2(a.z, a.w);
        p.z = packh2(b.x, b.y); p.w = packh2(b.z, b.w);
        *(uint4*)(d + i) = p;
    } else if (blk < 3328) {
        int idx = (blk - 3072) * 256 + tid;      // < BT_*RM_
        int bt = idx >> 5, m = idx & 31;
        float th = coords[bt] * W_rope[m];
        g_cost[idx] = cosf(th);
        g_sint[idx] = sinf(th);
    } else {
        int lb = blk - 3328;                     // 16 blocks
        int b  = lb >> 3;
        int idx = (lb & 7) * 256 + tid;
        if (idx < NBIAS_) {
            int dd = idx - (T_ - 1);
            const float* cb = coords + b * T_;
            float delta = (dd >= 0) ? (cb[dd] - cb[0]) : (cb[0] - cb[-dd]);
            float acc = 0.f;
            #pragma unroll
            for (int m = 0; m < FBM_; m++) {
                float S = delta * W_fb[m];
                acc += cosf(S) * bc[m] + sinf(S) * bs[m];
            }
            g_bias[b*NBIAS_ + idx] = acc * 0.17677669529663687f;  // 1/sqrt(FB_M)
        }
    }
}

// =============================================================================
// WMMA fp16 GEMM (fp16 inputs):  C[M,N] = A[M,K] * B[N,K]^T + bias (+ Res)
// 128xBN tile, 8 warps, K chunked by 32, double-buffered smem,
// LDG(next) issued before MMA(cur). FUSE: RoPE + fp16 head-split epilogue.
// =============================================================================
#define GST 40

template<bool FUSE, int BN>
__global__ __launch_bounds__(256, 2)
void gemm_wmma_kernel(const __half* __restrict__ A, const __half* __restrict__ Bm,
                      const float* __restrict__ bias, const float* __restrict__ Res,
                      float* __restrict__ Cout, int M, int N, int K) {
    constexpr int NJ = BN / 32;                  // j-fragments per warp
    constexpr int NQB = BN / 64;                 // B-load iterations
    extern __shared__ __align__(16) char smraw[];
    __half* Ah = (__half*)smraw;                 // [2][128*GST]
    __half* Bh = Ah + 2*128*GST;                 // [2][BN*GST]
    float* stage = (float*)(Bh + 2*BN*GST);      // 8 warps * 16*20 fp32

    const int tid  = threadIdx.x;
    const int w    = tid >> 5;
    const int lane = tid & 31;
    const int wm   = (w & 3) * 32;
    const int wn   = (w >> 2) * (BN/2);
    const int m0 = blockIdx.y * 128, n0 = blockIdx.x * BN;

    wmma::fragment<wmma::accumulator, 16, 16, 16, float> acc[2][NJ];
    #pragma unroll
    for (int i = 0; i < 2; i++)
        #pragma unroll
        for (int j = 0; j < NJ; j++) wmma::fill_fragment(acc[i][j], 0.0f);

    const int r_ld  = tid >> 2;          // row 0..63 (+64 per q)
    const int cg_ld = tid & 3;           // uint4 col group

    uint4 av[2], bv[NQB];
    // ---- prologue: LDG chunk 0 ----
    #pragma unroll
    for (int q = 0; q < 2; q++)
        av[q] = *(const uint4*)(A + (size_t)(m0 + r_ld + q*64) * K + cg_ld*8);
    #pragma unroll
    for (int q = 0; q < NQB; q++)
        bv[q] = *(const uint4*)(Bm + (size_t)(n0 + r_ld + q*64) * K + cg_ld*8);

    const int nch = K >> 5;
    for (int c = 0; c < nch; c++) {
        const int bs = c & 1;
        __half* Asm = Ah + bs * 128*GST;
        __half* Bsm = Bh + bs * BN*GST;
        // ---- STS ----
        #pragma unroll
        for (int q = 0; q < 2; q++)
            *(uint4*)&Asm[(r_ld + q*64)*GST + cg_ld*8] = av[q];
        #pragma unroll
        for (int q = 0; q < NQB; q++)
            *(uint4*)&Bsm[(r_ld + q*64)*GST + cg_ld*8] = bv[q];
        __syncthreads();
        // ---- LDG chunk c+1 (overlaps MMA below) ----
        if (c + 1 < nch) {
            const int k0 = (c + 1) * 32;
            #pragma unroll
            for (int q = 0; q < 2; q++)
                av[q] = *(const uint4*)(A + (size_t)(m0 + r_ld + q*64) * K + k0 + cg_ld*8);
            #pragma unroll
            for (int q = 0; q < NQB; q++)
                bv[q] = *(const uint4*)(Bm + (size_t)(n0 + r_ld + q*64) * K + k0 + cg_ld*8);
        }
        // ---- MMA chunk c ----
        #pragma unroll
        for (int kk = 0; kk < 2; kk++) {
            wmma::fragment<wmma::matrix_a, 16,16,16, __half, wmma::row_major> ah[2];
            #pragma unroll
            for (int i = 0; i < 2; i++)
                wmma::load_matrix_sync(ah[i], &Asm[(wm + i*16)*GST + kk*16], GST);
            #pragma unroll
            for (int j = 0; j < NJ; j++) {
                wmma::fragment<wmma::matrix_b, 16,16,16, __half, wmma::col_major> bf;
                wmma::load_matrix_sync(bf, &Bsm[(wn + j*16)*GST + kk*16], GST);
                #pragma unroll
                for (int i = 0; i < 2; i++)
                    wmma::mma_sync(acc[i][j], ah[i], bf, acc[i][j]);
            }
        }
    }

    // ---- epilogue ----
    float* st = stage + w * 16 * 20;
    #pragma unroll
    for (int i = 0; i < 2; i++) {
        #pragma unroll
        for (int j = 0; j < NJ; j++) {
            wmma::store_matrix_sync(st, acc[i][j], 20, wmma::mem_row_major);
            __syncwarp();
            int row = lane >> 1, ch = (lane & 1) * 8;
            int gm = m0 + wm + i*16 + row;
            int gn = n0 + wn + j*16 + ch;
            float4 o1 = *(float4*)&st[row*20 + ch];
            float4 o2 = *(float4*)&st[row*20 + ch + 4];
            float4 b1 = *(const float4*)(bias + gn);
            float4 b2 = *(const float4*)(bias + gn + 4);
            o1.x += b1.x; o1.y += b1.y; o1.z += b1.z; o1.w += b1.w;
            o2.x += b2.x; o2.y += b2.y; o2.z += b2.z; o2.w += b2.w;
            if (FUSE) {
                // RoPE + fp16 pack + [B,H,T,D] scatter
                int part = gn >> 10, hd = gn & 1023;
                int hh = hd >> 6, d = hd & 63;
                size_t dst = (((size_t)(gm >> 10) * H_ + hh) * T_ + (gm & 1023)) * D_ + d;
                uint4 pk;
                if (part < 2) {
                    float4 cs = *(const float4*)&g_cost[gm*RM_ + (d >> 1)];
                    float4 sn = *(const float4*)&g_sint[gm*RM_ + (d >> 1)];
                    pk.x = packh2(o1.x*cs.x - o1.y*sn.x, o1.x*sn.x + o1.y*cs.x);
                    pk.y = packh2(o1.z*cs.y - o1.w*sn.y, o1.z*sn.y + o1.w*cs.y);
                    pk.z = packh2(o2.x*cs.z - o2.y*sn.z, o2.x*sn.z + o2.y*cs.z);
                    pk.w = packh2(o2.z*cs.w - o2.w*sn.w, o2.z*sn.w + o2.w*cs.w);
                    *(uint4*)((part == 0 ? g_qf : g_kf) + dst) = pk;
                } else {
                    pk.x = packh2(o1.x, o1.y); pk.y = packh2(o1.z, o1.w);
                    pk.z = packh2(o2.x, o2.y); pk.w = packh2(o2.z, o2.w);
                    *(uint4*)(g_vf + dst) = pk;
                }
            } else {
                float4 r1 = *(const float4*)(Res + (size_t)gm * N + gn);
                float4 r2 = *(const float4*)(Res + (size_t)gm * N + gn + 4);
                o1.x += r1.x; o1.y += r1.y; o1.z += r1.z; o1.w += r1.w;
                o2.x += r2.x; o2.y += r2.y; o2.z += r2.z; o2.w += r2.w;
                *(float4*)(Cout + (size_t)gm * N + gn)     = o1;
                *(float4*)(Cout + (size_t)gm * N + gn + 4) = o2;
            }
            __syncwarp();
        }
    }
}

// =============================================================================
// Raw-PTX flash attention, fp16, q-tile 128 (8 warps x 16 rows), k-chunks 64,
// double-buffered K/V smem, LDG(next) before compute(cur), 2 CTAs/SM.
// =============================================================================
#define AKST 72   // smem row stride in fp16 elements

__global__ __launch_bounds__(256, 2)
void attn_mma_kernel() {
    __shared__ __align__(16) __half Kh[2][64*AKST];
    __shared__ __align__(16) __half Vh[2][64*AKST];
    __shared__ float bias_sm[1152];

    const int bh = blockIdx.y;
    const int b  = bh >> 4;
    const int h  = bh & 15;
    const int q0 = blockIdx.x * 128;
    const int tid  = threadIdx.x;
    const int w    = tid >> 5;
    const int lane = tid & 31;
    const int wq   = w * 16;

    // bias slice: idx for (local row rr, global col k) = 1023 + rr - k
    for (int i = tid; i < 1151; i += 256)
        bias_sm[i] = g_bias[b*NBIAS_ + q0 + i];

    // ---- stage Q (128x64 fp16) into Kh[0] (rows 0-63) + Vh[0] (rows 64-127) ----
    const uint4* qg = (const uint4*)(g_qf + ((size_t)bh * T_ + q0) * D_);
    #pragma unroll
    for (int qq = 0; qq < 4; qq++) {
        int id = qq * 256 + tid;
        int r = id >> 3, c = id & 7;
        __half* dst = (r < 64) ? &Kh[0][r*AKST + c*8] : &Vh[0][(r-64)*AKST + c*8];
        *(uint4*)dst = qg[r*8 + c];
    }
    __syncthreads();

    const uint32_t kb0 = smem_u32(Kh[0]), kb1 = smem_u32(Kh[1]);
    const uint32_t vb0 = smem_u32(Vh[0]), vb1 = smem_u32(Vh[1]);

    uint32_t qf[4][4];
    {
        const uint32_t qbase = (w < 4) ? kb0 : vb0;
        const int rbuf = (wq & 63) + (lane & 15);
        #pragma unroll
        for (int kk = 0; kk < 4; kk++) {
            uint32_t off = (uint32_t)((rbuf*AKST + kk*16 + (lane >> 4)*8) * 2);
            ldsm4(qf[kk], qbase + off);
        }
    }
    __syncthreads();   // Q frags read before chunk0 STS overwrites

    float oacc[8][4];
    #pragma unroll
    for (int j = 0; j < 8; j++)
        #pragma unroll
        for (int i = 0; i < 4; i++) oacc[j][i] = 0.f;
    float dsum0 = 0.f, dsum1 = 0.f;

    const __half* khg = g_kf + (size_t)bh * T_ * D_;
    const __half* vhg = g_vf + (size_t)bh * T_ * D_;
    const int i0base0 = 1023 + wq + (lane >> 2) - (lane & 3) * 2;

    // ---- prologue: LDG chunk 0 ----
    uint4 tK[2], tV[2];
    #pragma unroll
    for (int qq = 0; qq < 2; qq++) {
        int id = qq * 256 + tid;
        int r = id >> 3, c = id & 7;
        size_t g = (size_t)r * D_ + c * 8;
        tK[qq] = *(const uint4*)(khg + g);
        tV[qq] = *(const uint4*)(vhg + g);
    }

    for (int kc = 0; kc < 16; kc++) {
        const int k0 = kc * 64;
        const int bs = kc & 1;
        // ---- STS chunk kc ----
        #pragma unroll
        for (int qq = 0; qq < 2; qq++) {
            int id = qq * 256 + tid;
            int r = id >> 3, c = id & 7;
            *(uint4*)&Kh[bs][r*AKST + c*8] = tK[qq];
            *(uint4*)&Vh[bs][r*AKST + c*8] = tV[qq];
        }
        __syncthreads();
        // ---- LDG chunk kc+1 (overlaps compute below) ----
        if (kc < 15) {
            const int kn = (kc + 1) * 64;
            #pragma unroll
            for (int qq = 0; qq < 2; qq++) {
                int id = qq * 256 + tid;
                int r = id >> 3, c = id & 7;
                size_t g = (size_t)(kn + r) * D_ + c * 8;
                tK[qq] = *(const uint4*)(khg + g);
                tV[qq] = *(const uint4*)(vhg + g);
            }
        }
        const uint32_t kbh = bs ? kb1 : kb0;
        const uint32_t vbh = bs ? vb1 : vb0;

        // ---- S = Q K^T, accum in registers ----
        float sacc[8][4];
        #pragma unroll
        for (int j = 0; j < 8; j++)
            #pragma unroll
            for (int i = 0; i < 4; i++) sacc[j][i] = 0.f;

        #pragma unroll
        for (int kk = 0; kk < 4; kk++) {
            #pragma unroll
            for (int jp = 0; jp < 4; jp++) {
                uint32_t off = (uint32_t)(((jp*16 + ((lane>>4)<<3) + (lane&7)) * AKST
                               + kk*16 + ((lane>>3)&1)*8) * 2);
                uint32_t bhf[4];
                ldsm4(bhf, kbh + off);
                mma16816(sacc[jp*2],   qf[kk], bhf[0], bhf[1]);
                mma16816(sacc[jp*2+1], qf[kk], bhf[2], bhf[3]);
            }
        }

        // ---- softmax numerators in registers ----
        const int i0b = i0base0 - k0;
        #pragma unroll
        for (int j = 0; j < 8; j++) {
            int i0 = i0b - j*8;
            float p0 = __expf(sacc[j][0] * 0.125f + bias_sm[i0]);
            float p1 = __expf(sacc[j][1] * 0.125f + bias_sm[i0 - 1]);
            float p2 = __expf(sacc[j][2] * 0.125f + bias_sm[i0 + 8]);
            float p3 = __expf(sacc[j][3] * 0.125f + bias_sm[i0 + 7]);
            dsum0 += p0 + p1;
            dsum1 += p2 + p3;
            sacc[j][0] = p0; sacc[j][1] = p1; sacc[j][2] = p2; sacc[j][3] = p3;
        }

        // ---- O += P V (P from registers, V via ldmatrix.trans) ----
        #pragma unroll
        for (int kk = 0; kk < 4; kk++) {
            uint32_t pa[4];
            pa[0] = packh2(sacc[2*kk][0],   sacc[2*kk][1]);
            pa[1] = packh2(sacc[2*kk][2],   sacc[2*kk][3]);
            pa[2] = packh2(sacc[2*kk+1][0], sacc[2*kk+1][1]);
            pa[3] = packh2(sacc[2*kk+1][2], sacc[2*kk+1][3]);
            #pragma unroll
            for (int dp = 0; dp < 4; dp++) {
                uint32_t off = (uint32_t)(((kk*16 + ((lane>>3)&1)*8 + (lane&7)) * AKST
                               + dp*16 + (lane>>4)*8) * 2);
                uint32_t bvf[4];
                ldsm4t(bvf, vbh + off);
                mma16816(oacc[dp*2],   pa, bvf[0], bvf[1]);
                mma16816(oacc[dp*2+1], pa, bvf[2], bvf[3]);
            }
        }
    }

    // ---- normalize + store fp16 ----
    dsum0 += __shfl_xor_sync(0xffffffffu, dsum0, 1);
    dsum0 += __shfl_xor_sync(0xffffffffu, dsum0, 2);
    dsum1 += __shfl_xor_sync(0xffffffffu, dsum1, 1);
    dsum1 += __shfl_xor_sync(0xffffffffu, dsum1, 2);
    float inv0 = 1.0f / dsum0, inv1 = 1.0f / dsum1;

    int r0g = q0 + wq + (lane >> 2);
    __half* y0 = g_yh + (size_t)(b*T_ + r0g) * C_ + h*D_ + (lane & 3)*2;
    __half* y1 = y0 + (size_t)8 * C_;
    #pragma unroll
    for (int j = 0; j < 8; j++) {
        *(uint32_t*)(y0 + j*8) = packh2(oacc[j][0] * inv0, oacc[j][1] * inv0);
        *(uint32_t*)(y1 + j*8) = packh2(oacc[j][2] * inv1, oacc[j][3] * inv1);
    }
}

// ---------------- launcher ----------------------------------------------------
#define GEMM_SMEM_128 (2*128*GST*2 + 2*128*GST*2 + 8*16*20*4)   // 51200
#define GEMM_SMEM_64  (2*128*GST*2 + 2*64*GST*2  + 8*16*20*4)   // 40960

extern "C" void kernel_launch(void* const* d_in, const int* in_sizes, int n_in,
                              void* d_out, int out_size) {
    (void)in_sizes; (void)n_in; (void)out_size;
    const float* x      = (const float*)d_in[0];
    const float* coords = (const float*)d_in[1];
    const float* W_attn = (const float*)d_in[2];
    const float* b_attn = (const float*)d_in[3];
    const float* W_proj = (const float*)d_in[4];
    const float* b_proj = (const float*)d_in[5];
    const float* W_rope = (const float*)d_in[6];
    const float* W_fb   = (const float*)d_in[7];
    const float* bcos   = (const float*)d_in[8];
    const float* bsin   = (const float*)d_in[9];
    float* out = (float*)d_out;

    void *p_xh = nullptr, *p_wah = nullptr, *p_wph = nullptr, *p_yh = nullptr;
    cudaGetSymbolAddress(&p_xh,  g_xh);
    cudaGetSymbolAddress(&p_wah, g_wah);
    cudaGetSymbolAddress(&p_wph, g_wph);
    cudaGetSymbolAddress(&p_yh,  g_yh);

    static bool attr_set = false;
    if (!attr_set) {
        cudaFuncSetAttribute(gemm_wmma_kernel<true, 128>,
                             cudaFuncAttributeMaxDynamicSharedMemorySize, GEMM_SMEM_128);
        cudaFuncSetAttribute(gemm_wmma_kernel<false, 64>,
                             cudaFuncAttributeMaxDynamicSharedMemorySize, GEMM_SMEM_64);
        attr_set = true;
    }

    // ---- single fused prologue launch (cvt x / W_attn / W_proj + tables) ----
    prologue_kernel<<<PRO_BLOCKS, 256>>>(x, W_attn, W_proj, coords, W_rope,
                                         W_fb, bcos, bsin);

    // ---- main chain ----
    gemm_wmma_kernel<true, 128><<<dim3(C3_/128, BT_/128), 256, GEMM_SMEM_128>>>(
        (const __half*)p_xh, (const __half*)p_wah, b_attn, nullptr, nullptr,
        BT_, C3_, C_);

    attn_mma_kernel<<<dim3(T_/128, B_*H_), 256>>>();

    gemm_wmma_kernel<false, 64><<<dim3(C_/64, BT_/128), 256, GEMM_SMEM_64>>>(
        (const __half*)p_yh, (const __half*)p_wph, b_proj, x, out, BT_, C_, C_);
}

// round 17
// speedup vs baseline: 1.2745x; 1.2180x over previous
#include <cuda_runtime.h>
#include <cuda_fp16.h>
#include <mma.h>
#include <math.h>
#include <stdint.h>
#include <string.h>

using namespace nvcuda;

#define B_    2
#define T_    1024
#define C_    1024
#define H_    16
#define D_    64
#define RM_   32
#define FBM_  32
#define BT_   (B_*T_)       // 2048
#define C3_   (3*C_)        // 3072
#define NBIAS_ (2*T_-1)     // 2047

// ---------------- scratch (static device globals; no allocation) ------------
__device__ __half g_xh [BT_*C_];             // x in fp16 (gemm1 A)
__device__ __half g_wah[C3_*C_];             // W_attn fp16
__device__ __half g_wph[C_*C_];              // W_proj fp16
__device__ __half g_yh [BT_*C_];             // attention output fp16 (gemm2 A)
__device__ __half g_qf[BT_*C_];              // [B,H,T,D] fp16 (rope applied)
__device__ __half g_kf[BT_*C_];
__device__ __half g_vf[BT_*C_];
__device__ float g_cost[BT_*RM_];
__device__ float g_sint[BT_*RM_];
__device__ float g_bias[B_*NBIAS_];          // bias lookup by (q-k)+T-1

// ---------------- helpers ----------------------------------------------------
__device__ __forceinline__ uint32_t smem_u32(const void* p) {
    uint32_t a;
    asm("{ .reg .u64 t; cvta.to.shared.u64 t, %1; cvt.u32.u64 %0, t; }"
        : "=r"(a) : "l"(p));
    return a;
}

__device__ __forceinline__ uint32_t packh2(float p0, float p1) {
    __half2 h = __floats2half2_rn(p0, p1);   // .x = p0 (low half)
    uint32_t u; memcpy(&u, &h, 4);
    return u;
}

__device__ __forceinline__ void cp16(uint32_t dst, const void* src) {
    asm volatile("cp.async.cg.shared.global [%0], [%1], 16;"
        :: "r"(dst), "l"(src) : "memory");
}
#define CP_COMMIT() asm volatile("cp.async.commit_group;" ::: "memory")
#define CP_WAIT1()  asm volatile("cp.async.wait_group 1;" ::: "memory")

__device__ __forceinline__ void ldsm4(uint32_t* r, uint32_t addr) {
    asm volatile("ldmatrix.sync.aligned.m8n8.x4.shared.b16 {%0,%1,%2,%3}, [%4];"
        : "=r"(r[0]),"=r"(r[1]),"=r"(r[2]),"=r"(r[3]) : "r"(addr));
}
__device__ __forceinline__ void ldsm4t(uint32_t* r, uint32_t addr) {
    asm volatile("ldmatrix.sync.aligned.m8n8.x4.trans.shared.b16 {%0,%1,%2,%3}, [%4];"
        : "=r"(r[0]),"=r"(r[1]),"=r"(r[2]),"=r"(r[3]) : "r"(addr));
}
__device__ __forceinline__ void mma16816(float* d, const uint32_t* a,
                                         uint32_t b0, uint32_t b1) {
    asm volatile("mma.sync.aligned.m16n8k16.row.col.f32.f16.f16.f32 "
        "{%0,%1,%2,%3}, {%4,%5,%6,%7}, {%8,%9}, {%0,%1,%2,%3};"
        : "+f"(d[0]),"+f"(d[1]),"+f"(d[2]),"+f"(d[3])
        : "r"(a[0]),"r"(a[1]),"r"(a[2]),"r"(a[3]),"r"(b0),"r"(b1));
}

// =============================================================================
// Fused prologue (ONE launch, blockIdx-partitioned)
// =============================================================================
#define PRO_BLOCKS 3344

__global__ __launch_bounds__(256)
void prologue_kernel(const float* __restrict__ x,
                     const float* __restrict__ W_attn,
                     const float* __restrict__ W_proj,
                     const float* __restrict__ coords,
                     const float* __restrict__ W_rope,
                     const float* __restrict__ W_fb,
                     const float* __restrict__ bc,
                     const float* __restrict__ bs) {
    const int blk = blockIdx.x;
    const int tid = threadIdx.x;
    if (blk < 3072) {
        const float* s;
        __half* d;
        int lb;
        if (blk < 1024)      { s = x;      d = g_xh;  lb = blk; }
        else if (blk < 2560) { s = W_attn; d = g_wah; lb = blk - 1024; }
        else                 { s = W_proj; d = g_wph; lb = blk - 2560; }
        size_t i = ((size_t)lb * 256 + tid) * 8;
        float4 a = *(const float4*)(s + i);
        float4 b = *(const float4*)(s + i + 4);
        uint4 p;
        p.x = packh2(a.x, a.y); p.y = packh2(a.z, a.w);
        p.z = packh2(b.x, b.y); p.w = packh2(b.z, b.w);
        *(uint4*)(d + i) = p;
    } else if (blk < 3328) {
        int idx = (blk - 3072) * 256 + tid;      // < BT_*RM_
        int bt = idx >> 5, m = idx & 31;
        float th = coords[bt] * W_rope[m];
        g_cost[idx] = cosf(th);
        g_sint[idx] = sinf(th);
    } else {
        int lb = blk - 3328;                     // 16 blocks
        int b  = lb >> 3;
        int idx = (lb & 7) * 256 + tid;
        if (idx < NBIAS_) {
            int dd = idx - (T_ - 1);
            const float* cb = coords + b * T_;
            float delta = (dd >= 0) ? (cb[dd] - cb[0]) : (cb[0] - cb[-dd]);
            float acc = 0.f;
            #pragma unroll
            for (int m = 0; m < FBM_; m++) {
                float S = delta * W_fb[m];
                acc += cosf(S) * bc[m] + sinf(S) * bs[m];
            }
            g_bias[b*NBIAS_ + idx] = acc * 0.17677669529663687f;  // 1/sqrt(FB_M)
        }
    }
}

// =============================================================================
// WMMA fp16 GEMM, cp.async 3-stage pipeline:
//   C[M,N] = A[M,K] * B[N,K]^T + bias (+ Res)
// 128x128 tile, 8 warps of 32x64, K chunked by 32.
// FUSE: RoPE + fp16 head-split epilogue.
// =============================================================================
#define GST 40

template<bool FUSE>
__global__ __launch_bounds__(256, 2)
void gemm_wmma_kernel(const __half* __restrict__ A, const __half* __restrict__ Bm,
                      const float* __restrict__ bias, const float* __restrict__ Res,
                      float* __restrict__ Cout, int M, int N, int K) {
    constexpr int A_ELE = 128*GST;
    constexpr int B_ELE = 128*GST;
    constexpr int S_ELE = A_ELE + B_ELE;         // elems per stage
    extern __shared__ __align__(16) char smraw[];
    __half* sm = (__half*)smraw;                 // 3 stages [A | B]
    float* stage = (float*)smraw;                // epilogue overlay

    const int tid  = threadIdx.x;
    const int w    = tid >> 5;
    const int lane = tid & 31;
    const int wm   = (w & 3) * 32;
    const int wn   = (w >> 2) * 64;
    const int m0 = blockIdx.y * 128, n0 = blockIdx.x * 128;

    wmma::fragment<wmma::accumulator, 16, 16, 16, float> acc[2][4];
    #pragma unroll
    for (int i = 0; i < 2; i++)
        #pragma unroll
        for (int j = 0; j < 4; j++) wmma::fill_fragment(acc[i][j], 0.0f);

    // per-thread load geometry: 4 rows/warp, 16B per thread, rows r_ld & r_ld+64
    const int r_ld  = tid >> 2;
    const int cg_ld = tid & 3;
    const __half* aS0 = A  + (size_t)(m0 + r_ld)      * K + cg_ld*8;
    const __half* aS1 = A  + (size_t)(m0 + r_ld + 64) * K + cg_ld*8;
    const __half* bS0 = Bm + (size_t)(n0 + r_ld)      * K + cg_ld*8;
    const __half* bS1 = Bm + (size_t)(n0 + r_ld + 64) * K + cg_ld*8;
    const uint32_t smb = smem_u32(sm);
    const uint32_t aD0 = smb + (uint32_t)((r_ld*GST + cg_ld*8) * 2);
    const uint32_t aD1 = smb + (uint32_t)(((r_ld+64)*GST + cg_ld*8) * 2);
    const uint32_t bD0 = aD0 + A_ELE*2;
    const uint32_t bD1 = aD1 + A_ELE*2;

    const int nch = K >> 5;                      // 32 chunks

    // issue stage for chunk c (empty commit past the end keeps groups aligned)
    auto issue = [&](int c) {
        if (c < nch) {
            uint32_t so = (uint32_t)((c % 3) * S_ELE * 2);
            size_t ko = (size_t)c * 32;
            cp16(aD0 + so, aS0 + ko);
            cp16(aD1 + so, aS1 + ko);
            cp16(bD0 + so, bS0 + ko);
            cp16(bD1 + so, bS1 + ko);
        }
        CP_COMMIT();
    };

    issue(0);
    issue(1);

    for (int c = 0; c < nch; c++) {
        CP_WAIT1();            // stage c resident (this thread's copies)
        __syncthreads();       // ... and everyone else's
        issue(c + 2);          // overwrites stage of chunk c-1 (mma done last iter)

        const __half* Asm = sm + (c % 3) * S_ELE;
        const __half* Bsm = Asm + A_ELE;
        #pragma unroll
        for (int kk = 0; kk < 2; kk++) {
            wmma::fragment<wmma::matrix_a, 16,16,16, __half, wmma::row_major> ah[2];
            #pragma unroll
            for (int i = 0; i < 2; i++)
                wmma::load_matrix_sync(ah[i], &Asm[(wm + i*16)*GST + kk*16], GST);
            #pragma unroll
            for (int j = 0; j < 4; j++) {
                wmma::fragment<wmma::matrix_b, 16,16,16, __half, wmma::col_major> bf;
                wmma::load_matrix_sync(bf, &Bsm[(wn + j*16)*GST + kk*16], GST);
                #pragma unroll
                for (int i = 0; i < 2; i++)
                    wmma::mma_sync(acc[i][j], ah[i], bf, acc[i][j]);
            }
        }
    }

    // ---- epilogue (stage overlays pipeline buffers; all MMAs done) ----
    __syncthreads();
    float* st = stage + w * 16 * 20;
    #pragma unroll
    for (int i = 0; i < 2; i++) {
        #pragma unroll
        for (int j = 0; j < 4; j++) {
            wmma::store_matrix_sync(st, acc[i][j], 20, wmma::mem_row_major);
            __syncwarp();
            int row = lane >> 1, ch = (lane & 1) * 8;
            int gm = m0 + wm + i*16 + row;
            int gn = n0 + wn + j*16 + ch;
            float4 o1 = *(float4*)&st[row*20 + ch];
            float4 o2 = *(float4*)&st[row*20 + ch + 4];
            float4 b1 = *(const float4*)(bias + gn);
            float4 b2 = *(const float4*)(bias + gn + 4);
            o1.x += b1.x; o1.y += b1.y; o1.z += b1.z; o1.w += b1.w;
            o2.x += b2.x; o2.y += b2.y; o2.z += b2.z; o2.w += b2.w;
            if (FUSE) {
                // RoPE + fp16 pack + [B,H,T,D] scatter
                int part = gn >> 10, hd = gn & 1023;
                int hh = hd >> 6, d = hd & 63;
                size_t dst = (((size_t)(gm >> 10) * H_ + hh) * T_ + (gm & 1023)) * D_ + d;
                uint4 pk;
                if (part < 2) {
                    float4 cs = *(const float4*)&g_cost[gm*RM_ + (d >> 1)];
                    float4 sn = *(const float4*)&g_sint[gm*RM_ + (d >> 1)];
                    pk.x = packh2(o1.x*cs.x - o1.y*sn.x, o1.x*sn.x + o1.y*cs.x);
                    pk.y = packh2(o1.z*cs.y - o1.w*sn.y, o1.z*sn.y + o1.w*cs.y);
                    pk.z = packh2(o2.x*cs.z - o2.y*sn.z, o2.x*sn.z + o2.y*cs.z);
                    pk.w = packh2(o2.z*cs.w - o2.w*sn.w, o2.z*sn.w + o2.w*cs.w);
                    *(uint4*)((part == 0 ? g_qf : g_kf) + dst) = pk;
                } else {
                    pk.x = packh2(o1.x, o1.y); pk.y = packh2(o1.z, o1.w);
                    pk.z = packh2(o2.x, o2.y); pk.w = packh2(o2.z, o2.w);
                    *(uint4*)(g_vf + dst) = pk;
                }
            } else {
                float4 r1 = *(const float4*)(Res + (size_t)gm * N + gn);
                float4 r2 = *(const float4*)(Res + (size_t)gm * N + gn + 4);
                o1.x += r1.x; o1.y += r1.y; o1.z += r1.z; o1.w += r1.w;
                o2.x += r2.x; o2.y += r2.y; o2.z += r2.z; o2.w += r2.w;
                *(float4*)(Cout + (size_t)gm * N + gn)     = o1;
                *(float4*)(Cout + (size_t)gm * N + gn + 4) = o2;
            }
            __syncwarp();
        }
    }
}

// =============================================================================
// Raw-PTX flash attention, fp16, q-tile 128 (8 warps x 16 rows), k-chunks 64,
// double-buffered K/V smem, LDG(next) before compute(cur), 2 CTAs/SM.
// (unchanged from R16)
// =============================================================================
#define AKST 72   // smem row stride in fp16 elements

__global__ __launch_bounds__(256, 2)
void attn_mma_kernel() {
    __shared__ __align__(16) __half Kh[2][64*AKST];
    __shared__ __align__(16) __half Vh[2][64*AKST];
    __shared__ float bias_sm[1152];

    const int bh = blockIdx.y;
    const int b  = bh >> 4;
    const int h  = bh & 15;
    const int q0 = blockIdx.x * 128;
    const int tid  = threadIdx.x;
    const int w    = tid >> 5;
    const int lane = tid & 31;
    const int wq   = w * 16;

    for (int i = tid; i < 1151; i += 256)
        bias_sm[i] = g_bias[b*NBIAS_ + q0 + i];

    const uint4* qg = (const uint4*)(g_qf + ((size_t)bh * T_ + q0) * D_);
    #pragma unroll
    for (int qq = 0; qq < 4; qq++) {
        int id = qq * 256 + tid;
        int r = id >> 3, c = id & 7;
        __half* dst = (r < 64) ? &Kh[0][r*AKST + c*8] : &Vh[0][(r-64)*AKST + c*8];
        *(uint4*)dst = qg[r*8 + c];
    }
    __syncthreads();

    const uint32_t kb0 = smem_u32(Kh[0]), kb1 = smem_u32(Kh[1]);
    const uint32_t vb0 = smem_u32(Vh[0]), vb1 = smem_u32(Vh[1]);

    uint32_t qf[4][4];
    {
        const uint32_t qbase = (w < 4) ? kb0 : vb0;
        const int rbuf = (wq & 63) + (lane & 15);
        #pragma unroll
        for (int kk = 0; kk < 4; kk++) {
            uint32_t off = (uint32_t)((rbuf*AKST + kk*16 + (lane >> 4)*8) * 2);
            ldsm4(qf[kk], qbase + off);
        }
    }
    __syncthreads();

    float oacc[8][4];
    #pragma unroll
    for (int j = 0; j < 8; j++)
        #pragma unroll
        for (int i = 0; i < 4; i++) oacc[j][i] = 0.f;
    float dsum0 = 0.f, dsum1 = 0.f;

    const __half* khg = g_kf + (size_t)bh * T_ * D_;
    const __half* vhg = g_vf + (size_t)bh * T_ * D_;
    const int i0base0 = 1023 + wq + (lane >> 2) - (lane & 3) * 2;

    uint4 tK[2], tV[2];
    #pragma unroll
    for (int qq = 0; qq < 2; qq++) {
        int id = qq * 256 + tid;
        int r = id >> 3, c = id & 7;
        size_t g = (size_t)r * D_ + c * 8;
        tK[qq] = *(const uint4*)(khg + g);
        tV[qq] = *(const uint4*)(vhg + g);
    }

    for (int kc = 0; kc < 16; kc++) {
        const int k0 = kc * 64;
        const int bs = kc & 1;
        #pragma unroll
        for (int qq = 0; qq < 2; qq++) {
            int id = qq * 256 + tid;
            int r = id >> 3, c = id & 7;
            *(uint4*)&Kh[bs][r*AKST + c*8] = tK[qq];
            *(uint4*)&Vh[bs][r*AKST + c*8] = tV[qq];
        }
        __syncthreads();
        if (kc < 15) {
            const int kn = (kc + 1) * 64;
            #pragma unroll
            for (int qq = 0; qq < 2; qq++) {
                int id = qq * 256 + tid;
                int r = id >> 3, c = id & 7;
                size_t g = (size_t)(kn + r) * D_ + c * 8;
                tK[qq] = *(const uint4*)(khg + g);
                tV[qq] = *(const uint4*)(vhg + g);
            }
        }
        const uint32_t kbh = bs ? kb1 : kb0;
        const uint32_t vbh = bs ? vb1 : vb0;

        float sacc[8][4];
        #pragma unroll
        for (int j = 0; j < 8; j++)
            #pragma unroll
            for (int i = 0; i < 4; i++) sacc[j][i] = 0.f;

        #pragma unroll
        for (int kk = 0; kk < 4; kk++) {
            #pragma unroll
            for (int jp = 0; jp < 4; jp++) {
                uint32_t off = (uint32_t)(((jp*16 + ((lane>>4)<<3) + (lane&7)) * AKST
                               + kk*16 + ((lane>>3)&1)*8) * 2);
                uint32_t bhf[4];
                ldsm4(bhf, kbh + off);
                mma16816(sacc[jp*2],   qf[kk], bhf[0], bhf[1]);
                mma16816(sacc[jp*2+1], qf[kk], bhf[2], bhf[3]);
            }
        }

        const int i0b = i0base0 - k0;
        #pragma unroll
        for (int j = 0; j < 8; j++) {
            int i0 = i0b - j*8;
            float p0 = __expf(sacc[j][0] * 0.125f + bias_sm[i0]);
            float p1 = __expf(sacc[j][1] * 0.125f + bias_sm[i0 - 1]);
            float p2 = __expf(sacc[j][2] * 0.125f + bias_sm[i0 + 8]);
            float p3 = __expf(sacc[j][3] * 0.125f + bias_sm[i0 + 7]);
            dsum0 += p0 + p1;
            dsum1 += p2 + p3;
            sacc[j][0] = p0; sacc[j][1] = p1; sacc[j][2] = p2; sacc[j][3] = p3;
        }

        #pragma unroll
        for (int kk = 0; kk < 4; kk++) {
            uint32_t pa[4];
            pa[0] = packh2(sacc[2*kk][0],   sacc[2*kk][1]);
            pa[1] = packh2(sacc[2*kk][2],   sacc[2*kk][3]);
            pa[2] = packh2(sacc[2*kk+1][0], sacc[2*kk+1][1]);
            pa[3] = packh2(sacc[2*kk+1][2], sacc[2*kk+1][3]);
            #pragma unroll
            for (int dp = 0; dp < 4; dp++) {
                uint32_t off = (uint32_t)(((kk*16 + ((lane>>3)&1)*8 + (lane&7)) * AKST
                               + dp*16 + (lane>>4)*8) * 2);
                uint32_t bvf[4];
                ldsm4t(bvf, vbh + off);
                mma16816(oacc[dp*2],   pa, bvf[0], bvf[1]);
                mma16816(oacc[dp*2+1], pa, bvf[2], bvf[3]);
            }
        }
    }

    dsum0 += __shfl_xor_sync(0xffffffffu, dsum0, 1);
    dsum0 += __shfl_xor_sync(0xffffffffu, dsum0, 2);
    dsum1 += __shfl_xor_sync(0xffffffffu, dsum1, 1);
    dsum1 += __shfl_xor_sync(0xffffffffu, dsum1, 2);
    float inv0 = 1.0f / dsum0, inv1 = 1.0f / dsum1;

    int r0g = q0 + wq + (lane >> 2);
    __half* y0 = g_yh + (size_t)(b*T_ + r0g) * C_ + h*D_ + (lane & 3)*2;
    __half* y1 = y0 + (size_t)8 * C_;
    #pragma unroll
    for (int j = 0; j < 8; j++) {
        *(uint32_t*)(y0 + j*8) = packh2(oacc[j][0] * inv0, oacc[j][1] * inv0);
        *(uint32_t*)(y1 + j*8) = packh2(oacc[j][2] * inv1, oacc[j][3] * inv1);
    }
}

// ---------------- launcher ----------------------------------------------------
#define GEMM_SMEM (3 * (128*GST + 128*GST) * 2)             // 61440

extern "C" void kernel_launch(void* const* d_in, const int* in_sizes, int n_in,
                              void* d_out, int out_size) {
    (void)in_sizes; (void)n_in; (void)out_size;
    const float* x      = (const float*)d_in[0];
    const float* coords = (const float*)d_in[1];
    const float* W_attn = (const float*)d_in[2];
    const float* b_attn = (const float*)d_in[3];
    const float* W_proj = (const float*)d_in[4];
    const float* b_proj = (const float*)d_in[5];
    const float* W_rope = (const float*)d_in[6];
    const float* W_fb   = (const float*)d_in[7];
    const float* bcos   = (const float*)d_in[8];
    const float* bsin   = (const float*)d_in[9];
    float* out = (float*)d_out;

    void *p_xh = nullptr, *p_wah = nullptr, *p_wph = nullptr, *p_yh = nullptr;
    cudaGetSymbolAddress(&p_xh,  g_xh);
    cudaGetSymbolAddress(&p_wah, g_wah);
    cudaGetSymbolAddress(&p_wph, g_wph);
    cudaGetSymbolAddress(&p_yh,  g_yh);

    static bool attr_set = false;
    if (!attr_set) {
        cudaFuncSetAttribute(gemm_wmma_kernel<true>,
                             cudaFuncAttributeMaxDynamicSharedMemorySize, GEMM_SMEM);
        cudaFuncSetAttribute(gemm_wmma_kernel<false>,
                             cudaFuncAttributeMaxDynamicSharedMemorySize, GEMM_SMEM);
        attr_set = true;
    }

    // ---- single fused prologue launch (cvt x / W_attn / W_proj + tables) ----
    prologue_kernel<<<PRO_BLOCKS, 256>>>(x, W_attn, W_proj, coords, W_rope,
                                         W_fb, bcos, bsin);

    // ---- main chain ----
    gemm_wmma_kernel<true><<<dim3(C3_/128, BT_/128), 256, GEMM_SMEM>>>(
        (const __half*)p_xh, (const __half*)p_wah, b_attn, nullptr, nullptr,
        BT_, C3_, C_);

    attn_mma_kernel<<<dim3(T_/128, B_*H_), 256>>>();

    gemm_wmma_kernel<false><<<dim3(C_/128, BT_/128), 256, GEMM_SMEM>>>(
        (const __half*)p_yh, (const __half*)p_wph, b_proj, x, out, BT_, C_, C_);
}